// round 16
// baseline (speedup 1.0000x reference)
#include <cuda_runtime.h>
#include <cuda_bf16.h>
#include <cstdint>

#define K_CODES 8192
#define D_DIM   256
#define N_ROWS  32768
#define GAMMA_F 0.99f
#define EPS_F   1e-5f

// Output layout (float32, flattened tuple in reference order)
#define OFF_ZQ     0
#define OFF_COMMIT 8388608
#define OFF_IDX    8388609
#define OFF_EMB    8421377
#define OFF_MT     10518529
#define OFF_NT     12615681

#define ROW_TILES (N_ROWS / 128)    // 256
#define COL_TILES (K_CODES / 128)   // 64
#define COLG 8                      // col tiles per CTA
#define NSTEP (COLG * 4)            // 32 B-steps (8 tiles x 4 ksegs of 64)
#define MARGIN 0.5f                 // >20 sigma of bf16 phase-1 score error

// ---- scratch (device globals; no allocations allowed) ----
__device__ __nv_bfloat16 g_Ah[(size_t)N_ROWS * D_DIM];   // 16 MB
__device__ __nv_bfloat16 g_Bh[(size_t)K_CODES * D_DIM];  // 4 MB
__device__ unsigned long long g_tb[(size_t)N_ROWS * COL_TILES];  // 16 MB
__device__ unsigned long long g_best[N_ROWS];
__device__ int  g_list[(size_t)COL_TILES * N_ROWS];              // 8 MB
__device__ unsigned int g_cnt[COL_TILES];
__device__ float g_hn[K_CODES];
__device__ float g_nt[K_CODES];
__device__ float g_st[K_CODES * D_DIM];
__device__ float g_sse;
__device__ float g_nsum;

// ============================ PTX helpers (base ISA only) ============================
__device__ __forceinline__ uint32_t smem_u32(const void* p) {
    uint32_t a;
    asm("{ .reg .u64 t; cvta.to.shared.u64 t, %1; cvt.u32.u64 %0, t; }"
        : "=r"(a) : "l"(p));
    return a;
}

#define CP_ASYNC16(s, g) \
    asm volatile("cp.async.cg.shared.global [%0], [%1], 16;" :: "r"(s), "l"(g))
#define CP_COMMIT() asm volatile("cp.async.commit_group;" ::: "memory")
#define CP_WAIT(n)  asm volatile("cp.async.wait_group %0;" :: "n"(n) : "memory")

#define LDSM_X4(r0, r1, r2, r3, addr) \
    asm volatile("ldmatrix.sync.aligned.m8n8.x4.shared.b16 {%0,%1,%2,%3}, [%4];" \
                 : "=r"(r0), "=r"(r1), "=r"(r2), "=r"(r3) : "r"(addr))

#define MMA_BF16(c, a, b0, b1) \
    asm volatile("mma.sync.aligned.m16n8k16.row.col.f32.bf16.bf16.f32 " \
                 "{%0,%1,%2,%3}, {%4,%5,%6,%7}, {%8,%9}, {%0,%1,%2,%3};" \
                 : "+f"((c)[0]), "+f"((c)[1]), "+f"((c)[2]), "+f"((c)[3]) \
                 : "r"((a)[0]), "r"((a)[1]), "r"((a)[2]), "r"((a)[3]), \
                   "r"(b0), "r"(b1))

__device__ __forceinline__ unsigned long long pack_key(float s, int col) {
    unsigned u = __float_as_uint(s);
    unsigned key = (u & 0x80000000u) ? ~u : (u | 0x80000000u);
    return ((unsigned long long)key << 32) | (unsigned)(0x0FFFFFFF - col);
}
__device__ __forceinline__ float key_score(unsigned long long pk) {
    unsigned key = (unsigned)(pk >> 32);
    unsigned u = (key & 0x80000000u) ? (key & 0x7FFFFFFFu) : ~key;
    return __uint_as_float(u);
}

// ---------------------------------------------------------------------------
// 1) half squared norms: hn[k] = 0.5 * ||W_k||^2   (exact fp32)
// ---------------------------------------------------------------------------
__global__ void compute_hn(const float* __restrict__ W) {
    int row  = blockIdx.x * 8 + (threadIdx.x >> 5);
    int lane = threadIdx.x & 31;
    const float4* wr = (const float4*)W + (size_t)row * 64;
    float4 a = wr[lane];
    float4 b = wr[lane + 32];
    float s = a.x*a.x + a.y*a.y + a.z*a.z + a.w*a.w
            + b.x*b.x + b.y*b.y + b.z*b.z + b.w*b.w;
    #pragma unroll
    for (int off = 16; off > 0; off >>= 1)
        s += __shfl_down_sync(0xffffffffu, s, off);
    if (lane == 0) g_hn[row] = 0.5f * s;
}

// ---------------------------------------------------------------------------
// 2) bf16 rounding (phase-1 GEMM input)
// ---------------------------------------------------------------------------
__global__ void split_A(const float4* __restrict__ z4) {
    int i = blockIdx.x * 256 + threadIdx.x;   // N_ROWS*64 float4s
    float4 v = z4[i];
    __nv_bfloat162 lo = __floats2bfloat162_rn(v.x, v.y);
    __nv_bfloat162 hi = __floats2bfloat162_rn(v.z, v.w);
    uint2 pk = { *(uint32_t*)&lo, *(uint32_t*)&hi };
    ((uint2*)g_Ah)[i] = pk;
}
__global__ void split_B(const float4* __restrict__ w4) {
    int i = blockIdx.x * 256 + threadIdx.x;   // K_CODES*64 float4s
    float4 v = w4[i];
    __nv_bfloat162 lo = __floats2bfloat162_rn(v.x, v.y);
    __nv_bfloat162 hi = __floats2bfloat162_rn(v.z, v.w);
    uint2 pk = { *(uint32_t*)&lo, *(uint32_t*)&hi };
    ((uint2*)g_Bh)[i] = pk;
}

// ---------------------------------------------------------------------------
// 3) Phase-1: bf16 GEMM (K=256) + per-(row, col-tile) approx best.
//    A-resident multi-tile CTA: 128 rows x (8 tiles of 128 cols).
//    A tile 64KB resident (4 panels of BK=64); B streamed in 2-stage 16KB
//    pipeline over 32 flat steps. 8 warps (2m x 4n), mma.m16n8k16.bf16.
// ---------------------------------------------------------------------------
#define A_OFF   0                   // 4 panels * 16384
#define B_OFF   65536               // 2 stages * 16384
#define HN_OFF  98304               // 1024 floats
#define SB_OFF  102400              // 128 u64
#define SM_TOTAL (SB_OFF + 1024)    // 103424 bytes

// load B step u: col tile (u>>2) of this CTA's group, kseg (u&3)
__device__ __forceinline__ void load_B(uint32_t sstage,
                                       const __nv_bfloat16* __restrict__ Bgrp,
                                       int u, int tid) {
    const __nv_bfloat16* Bp = Bgrp + (size_t)(u >> 2) * (128 * D_DIM) + (u & 3) * 64;
    #pragma unroll
    for (int gi = 0; gi < 4; gi++) {
        int q = tid + gi * 256;          // 1024 granules
        int r = q >> 3, c = q & 7;
        uint32_t off = (uint32_t)(r * 128 + c * 16);
        uint32_t sw = off ^ ((off >> 3) & 0x70);
        CP_ASYNC16(sstage + sw, Bp + (size_t)r * D_DIM + c * 8);
    }
}

__global__ __launch_bounds__(256, 2) void gemm_p1() {
    extern __shared__ char smem[];
    const uint32_t sb = smem_u32(smem);
    const int tid = threadIdx.x, lid = tid & 31, wid = tid >> 5;
    const int wm = wid & 1, wn = wid >> 1;
    const int rowT = blockIdx.x >> 3, colG = blockIdx.x & 7;
    const int row0 = rowT * 128;
    const int colbase = colG * (COLG * 128);

    if (blockIdx.x == 0 && tid < COL_TILES) g_cnt[tid] = 0;  // for rowreduce

    float* hn_s = (float*)(smem + HN_OFF);
    unsigned long long* sbest = (unsigned long long*)(smem + SB_OFF);
    for (int i = tid; i < COLG * 128; i += 256) hn_s[i] = g_hn[colbase + i];
    if (tid < 128) sbest[tid] = 0ull;

    // ---- prologue: resident A (4 panels) + B steps 0,1 ----
    {
        const __nv_bfloat16* Ag = g_Ah + (size_t)row0 * D_DIM;
        #pragma unroll
        for (int gi = 0; gi < 16; gi++) {
            int q = tid + gi * 256;          // 4096 granules
            int r = q >> 5, c = q & 31;      // row, 16B-chunk of 512B row
            int kb = c >> 3, cc = c & 7;
            uint32_t off = (uint32_t)(r * 128 + cc * 16);
            uint32_t sw = off ^ ((off >> 3) & 0x70);
            CP_ASYNC16(sb + A_OFF + kb * 16384 + sw, Ag + (size_t)r * D_DIM + c * 8);
        }
        CP_COMMIT();
    }
    const __nv_bfloat16* Bgrp = g_Bh + (size_t)colbase * D_DIM;
    load_B(sb + B_OFF,         Bgrp, 0, tid); CP_COMMIT();
    load_B(sb + B_OFF + 16384, Bgrp, 1, tid); CP_COMMIT();
    CP_WAIT(1);                 // A + B0 done (B1 may be pending)
    __syncthreads();

    float c[4][4][4];
    #pragma unroll
    for (int i = 0; i < 4; i++)
        #pragma unroll
        for (int j = 0; j < 4; j++)
            #pragma unroll
            for (int q = 0; q < 4; q++) c[i][j][q] = 0.0f;

    // ldmatrix lane address components (m16n8k16 bf16 fragment mappings)
    const int rA  = (lid & 7) + ((lid >> 3) & 1) * 8;   // + wm*64 + mt*16
    const int cA  = (lid >> 4) & 1;
    const int rB  = (lid & 7) + ((lid >> 4) & 1) * 8;   // + wn*32 + p*16
    const int cB  = (lid >> 3) & 1;
    const int g = lid >> 2, t4 = lid & 3;

    for (int s = 0; s < NSTEP; s++) {
        // ---- compute step s: A panel (s&3) x B stage (s&1) ----
        const uint32_t sA = sb + A_OFF + (s & 3) * 16384;
        const uint32_t sB = sb + B_OFF + (s & 1) * 16384;
        #pragma unroll
        for (int ks = 0; ks < 4; ks++) {              // 4 x k16 = 64
            uint32_t a[4][4], b[2][4];
            #pragma unroll
            for (int mt = 0; mt < 4; mt++) {
                uint32_t off = (uint32_t)((wm * 64 + mt * 16 + rA) * 128
                                          + ks * 32 + cA * 16);
                LDSM_X4(a[mt][0], a[mt][1], a[mt][2], a[mt][3],
                        sA + (off ^ ((off >> 3) & 0x70)));
            }
            #pragma unroll
            for (int p = 0; p < 2; p++) {
                uint32_t off = (uint32_t)((wn * 32 + p * 16 + rB) * 128
                                          + ks * 32 + cB * 16);
                LDSM_X4(b[p][0], b[p][1], b[p][2], b[p][3],
                        sB + (off ^ ((off >> 3) & 0x70)));
            }
            #pragma unroll
            for (int mt = 0; mt < 4; mt++)
                #pragma unroll
                for (int nt = 0; nt < 4; nt++)
                    MMA_BF16(c[mt][nt], a[mt],
                             b[nt >> 1][(nt & 1) * 2 + 0],
                             b[nt >> 1][(nt & 1) * 2 + 1]);
        }

        // ---- epilogue when a tile completes (kseg == 3) ----
        if ((s & 3) == 3) {
            const int tl = s >> 2;
            const int col0 = colbase + tl * 128;
            #pragma unroll
            for (int mt = 0; mt < 4; mt++) {
                #pragma unroll
                for (int rr = 0; rr < 2; rr++) {
                    float best = -3.0e38f;
                    int bc = 0;
                    #pragma unroll
                    for (int nt = 0; nt < 4; nt++) {
                        #pragma unroll
                        for (int j = 0; j < 2; j++) {
                            int ccol = wn * 32 + nt * 8 + 2 * t4 + j;
                            float v = c[mt][nt][rr * 2 + j] - hn_s[tl * 128 + ccol];
                            if (v > best) { best = v; bc = ccol; }
                        }
                    }
                    #pragma unroll
                    for (int off = 1; off <= 2; off <<= 1) {
                        float ov = __shfl_xor_sync(0xffffffffu, best, off);
                        int   oc = __shfl_xor_sync(0xffffffffu, bc, off);
                        if (ov > best || (ov == best && oc < bc)) { best = ov; bc = oc; }
                    }
                    if (t4 == 0)
                        atomicMax(&sbest[wm * 64 + mt * 16 + rr * 8 + g],
                                  pack_key(best, col0 + bc));
                }
            }
            __syncthreads();
            if (tid < 128) {
                g_tb[(size_t)(row0 + tid) * COL_TILES + colG * COLG + tl] = sbest[tid];
                sbest[tid] = 0ull;
            }
            // reset accumulators for next tile
            #pragma unroll
            for (int i = 0; i < 4; i++)
                #pragma unroll
                for (int j = 0; j < 4; j++)
                    #pragma unroll
                    for (int q = 0; q < 4; q++) c[i][j][q] = 0.0f;
        }

        // ---- pipeline advance ----
        __syncthreads();                       // all warps done with B stage s&1
        if (s + 2 < NSTEP) {
            load_B(sb + B_OFF + (s & 1) * 16384, Bgrp, s + 2, tid);
            CP_COMMIT();
        }
        if (s + 1 < NSTEP) {
            CP_WAIT(1);                        // B_{s+1} complete
            __syncthreads();                   // visible to all threads
        }
    }
}

// ---------------------------------------------------------------------------
// 4) per-row reduce over 64 tiles; build candidate tile lists (margin filter)
// ---------------------------------------------------------------------------
__global__ void rowreduce() {
    int row  = blockIdx.x * 8 + (threadIdx.x >> 5);
    int lane = threadIdx.x & 31;
    if (blockIdx.x == 0 && threadIdx.x == 0) g_sse = 0.0f;

    unsigned long long a = g_tb[(size_t)row * COL_TILES + lane];
    unsigned long long b = g_tb[(size_t)row * COL_TILES + lane + 32];
    unsigned long long m = a > b ? a : b;
    #pragma unroll
    for (int off = 16; off > 0; off >>= 1) {
        unsigned long long o = __shfl_xor_sync(0xffffffffu, m, off);
        if (o > m) m = o;
    }
    float thr = key_score(m) - MARGIN;
    if (key_score(a) >= thr) {
        unsigned slot = atomicAdd(&g_cnt[lane], 1u);
        g_list[(size_t)lane * N_ROWS + slot] = row;
    }
    if (key_score(b) >= thr) {
        unsigned slot = atomicAdd(&g_cnt[lane + 32], 1u);
        g_list[(size_t)(lane + 32) * N_ROWS + slot] = row;
    }
    if (lane == 0) g_best[row] = 0ull;
}

// ---------------------------------------------------------------------------
// 5) exact fp32 rescore of candidate (row, tile) pairs; merge via atomicMax
//    grid = 64 tiles x 8 CTAs; block 256 (8 warps); 8-row batches per warp.
// ---------------------------------------------------------------------------
#define WT_STRIDE 257
#define RS_WT_FLOATS (128 * WT_STRIDE)                 // 32896
#define RS_Z_OFF   RS_WT_FLOATS
#define RS_HN_OFF  (RS_Z_OFF + 8 * 8 * 256)
#define RS_SMEM    ((RS_HN_OFF + 128) * 4)             // bytes

__global__ __launch_bounds__(256, 1) void rescore(const float* __restrict__ ze,
                                                  const float* __restrict__ W) {
    extern __shared__ float sm[];
    float* Wt   = sm;
    float* zall = sm + RS_Z_OFF;
    float* hn_s = sm + RS_HN_OFF;

    const int tid = threadIdx.x, lane = tid & 31, warp = tid >> 5;
    const int tile = blockIdx.x >> 3, sub = blockIdx.x & 7;
    const int col0 = tile * 128;
    const unsigned cnt = g_cnt[tile];

    // load W tile [128 cols][256 d] fp32 -> stride-257 smem (conflict-free)
    const float4* W4 = (const float4*)W;
    for (int idx = tid; idx < 128 * 64; idx += 256) {
        int col = idx >> 6, d4 = idx & 63;
        float4 v = W4[(size_t)(col0 + col) * 64 + d4];
        float* p = Wt + col * WT_STRIDE + d4 * 4;
        p[0] = v.x; p[1] = v.y; p[2] = v.z; p[3] = v.w;
    }
    if (tid < 128) hn_s[tid] = g_hn[col0 + tid];
    __syncthreads();

    const float4* z4 = (const float4*)ze;
    float* zb = zall + warp * (8 * 256);
    const int warpg = sub * 8 + warp;                 // 0..63
    const unsigned nbatch = (cnt + 7) >> 3;

    for (unsigned b = warpg; b < nbatch; b += 64) {
        int rows[8];
        int nval = (int)cnt - (int)(b * 8);
        if (nval > 8) nval = 8;
        #pragma unroll
        for (int r = 0; r < 8; r++) {
            int li = (int)(b * 8) + r;
            rows[r] = g_list[(size_t)tile * N_ROWS + (r < nval ? li : (int)(b * 8))];
        }
        #pragma unroll
        for (int r = 0; r < 8; r++) {
            float4 z0 = z4[(size_t)rows[r] * 64 + lane * 2];
            float4 z1 = z4[(size_t)rows[r] * 64 + lane * 2 + 1];
            *(float4*)(zb + r * 256 + lane * 8)     = z0;
            *(float4*)(zb + r * 256 + lane * 8 + 4) = z1;
        }
        __syncwarp();

        float acc[8][4];
        #pragma unroll
        for (int r = 0; r < 8; r++)
            #pragma unroll
            for (int q = 0; q < 4; q++) acc[r][q] = 0.0f;

        for (int d4 = 0; d4 < 64; d4++) {
            float w[4][4];
            #pragma unroll
            for (int q = 0; q < 4; q++) {
                const float* wp = Wt + (lane + 32 * q) * WT_STRIDE + d4 * 4;
                w[q][0] = wp[0]; w[q][1] = wp[1]; w[q][2] = wp[2]; w[q][3] = wp[3];
            }
            #pragma unroll
            for (int r = 0; r < 8; r++) {
                float4 z = *(const float4*)(zb + r * 256 + d4 * 4);
                #pragma unroll
                for (int q = 0; q < 4; q++)
                    acc[r][q] += z.x * w[q][0] + z.y * w[q][1]
                               + z.z * w[q][2] + z.w * w[q][3];
            }
        }

        #pragma unroll
        for (int r = 0; r < 8; r++) {
            if (r >= nval) break;        // warp-uniform
            float best = -3.0e38f;
            int bc = 0;
            #pragma unroll
            for (int q = 0; q < 4; q++) {
                int ccol = lane + 32 * q;
                float s = acc[r][q] - hn_s[ccol];
                if (s > best) { best = s; bc = ccol; }
            }
            #pragma unroll
            for (int off = 1; off <= 16; off <<= 1) {
                float ov = __shfl_xor_sync(0xffffffffu, best, off);
                int   oc = __shfl_xor_sync(0xffffffffu, bc, off);
                if (ov > best || (ov == best && oc < bc)) { best = ov; bc = oc; }
            }
            if (lane == 0)
                atomicMax(&g_best[rows[r]], pack_key(best, col0 + bc));
        }
        __syncwarp();
    }
}

// ---------------------------------------------------------------------------
// 6) gather zq, commit-loss partials, scatter EMA sums/counts
//    4 rows per 256-thread block (64-thread slices) for better load MLP.
// ---------------------------------------------------------------------------
__global__ void gather_scatter(const float* __restrict__ ze,
                               const float* __restrict__ W,
                               float* __restrict__ out)
{
    __shared__ float wsum[4][2];
    const int slice = threadIdx.x >> 6;   // 0..3
    const int t     = threadIdx.x & 63;   // float4 per thread
    const int row   = blockIdx.x * 4 + slice;
    if (row == 0 && t == 0) g_nsum = 0.0f;
    unsigned long long pk = g_best[row];
    int k = 0x0FFFFFFF - (int)(unsigned)(pk & 0xFFFFFFFFu);

    float4 z = ((const float4*)ze)[(size_t)row * 64 + t];
    float4 w = ((const float4*)W)[(size_t)k * 64 + t];

    ((float4*)(out + OFF_ZQ))[(size_t)row * 64 + t] = w;

    float dx = w.x - z.x, dy = w.y - z.y, dz = w.z - z.z, dw = w.w - z.w;
    float ss = dx*dx + dy*dy + dz*dz + dw*dw;

    int base = k * D_DIM + 4 * t;
    atomicAdd(&g_st[base + 0], z.x);
    atomicAdd(&g_st[base + 1], z.y);
    atomicAdd(&g_st[base + 2], z.z);
    atomicAdd(&g_st[base + 3], z.w);

    #pragma unroll
    for (int off = 16; off > 0; off >>= 1)
        ss += __shfl_down_sync(0xffffffffu, ss, off);
    if ((t & 31) == 0) wsum[slice][t >> 5] = ss;
    __syncthreads();
    if (t == 0) {
        atomicAdd(&g_sse, wsum[slice][0] + wsum[slice][1]);
        atomicAdd(&g_nt[k], 1.0f);
        out[OFF_IDX + row] = (float)k;
    }
}

// ---------------------------------------------------------------------------
// 7) Nt_new + total count n + commit scalar
// ---------------------------------------------------------------------------
__global__ void finalizeN(const float* __restrict__ Nt, float* __restrict__ out) {
    int k = blockIdx.x * 256 + threadIdx.x;
    float v = GAMMA_F * Nt[k] + (1.0f - GAMMA_F) * g_nt[k];
    out[OFF_NT + k] = v;

    float s = v;
    #pragma unroll
    for (int off = 16; off > 0; off >>= 1)
        s += __shfl_down_sync(0xffffffffu, s, off);
    __shared__ float bs[8];
    if ((threadIdx.x & 31) == 0) bs[threadIdx.x >> 5] = s;
    __syncthreads();
    if (threadIdx.x == 0) {
        float b = 0.0f;
        #pragma unroll
        for (int w = 0; w < 8; w++) b += bs[w];
        atomicAdd(&g_nsum, b);
    }
    if (blockIdx.x == 0 && threadIdx.x == 0)
        out[OFF_COMMIT] = g_sse * (1.0f / (float)(N_ROWS * D_DIM));
}

// ---------------------------------------------------------------------------
// 8) mt_new, embedW_new = mt_new / Nn; read-then-zero the EMA scratch
// ---------------------------------------------------------------------------
__global__ void finalizeW(const float* __restrict__ mt,
                          const float* __restrict__ Nt,
                          float* __restrict__ out)
{
    int k = blockIdx.x;
    int d = threadIdx.x;
    float n   = g_nsum;
    float Ntn = GAMMA_F * Nt[k] + (1.0f - GAMMA_F) * g_nt[k];
    float inv = (n + (float)K_CODES * EPS_F) / ((Ntn + EPS_F) * n);
    int q = k * D_DIM + d;
    float m = GAMMA_F * mt[q] + (1.0f - GAMMA_F) * g_st[q];
    out[OFF_MT  + q] = m;
    out[OFF_EMB + q] = m * inv;
    g_st[q] = 0.0f;                       // re-zero for next graph replay
    __syncthreads();
    if (d == 0) g_nt[k] = 0.0f;
}

// ---------------------------------------------------------------------------
extern "C" void kernel_launch(void* const* d_in, const int* in_sizes, int n_in,
                              void* d_out, int out_size)
{
    const float* ze = (const float*)d_in[0];
    const float* W  = (const float*)d_in[1];
    const float* mt = (const float*)d_in[2];
    const float* Nt = (const float*)d_in[3];
    float* out = (float*)d_out;

    cudaFuncSetAttribute(gemm_p1,
                         cudaFuncAttributeMaxDynamicSharedMemorySize, SM_TOTAL);
    cudaFuncSetAttribute(rescore,
                         cudaFuncAttributeMaxDynamicSharedMemorySize, RS_SMEM);

    compute_hn    <<<K_CODES / 8, 256>>> (W);
    split_A       <<<N_ROWS * 64 / 256, 256>>> ((const float4*)ze);
    split_B       <<<K_CODES * 64 / 256, 256>>> ((const float4*)W);
    gemm_p1       <<<ROW_TILES * 8, 256, SM_TOTAL>>> ();
    rowreduce     <<<N_ROWS / 8, 256>>> ();
    rescore       <<<COL_TILES * 8, 256, RS_SMEM>>> (ze, W);
    gather_scatter<<<N_ROWS / 4, 256>>> (ze, W, out);
    finalizeN     <<<K_CODES / 256, 256>>> (Nt, out);
    finalizeW     <<<K_CODES, 256>>> (mt, Nt, out);
}

// round 17
// speedup vs baseline: 1.0759x; 1.0759x over previous
#include <cuda_runtime.h>
#include <cuda_fp16.h>
#include <cstdint>

#define K_CODES 8192
#define D_DIM   256
#define N_ROWS  32768
#define GAMMA_F 0.99f
#define EPS_F   1e-5f

// Output layout (float32, flattened tuple in reference order)
#define OFF_ZQ     0
#define OFF_COMMIT 8388608
#define OFF_IDX    8388609
#define OFF_EMB    8421377
#define OFF_MT     10518529
#define OFF_NT     12615681

#define ROW_TILES (N_ROWS / 128)    // 256
#define COL_TILES (K_CODES / 128)   // 64
#define NCH 4                       // K-chunks of 64 fp16 (K=256)
#define MARGIN 1.0f                 // ~16 sigma of fp16-accum phase-1 error

// ---- scratch (device globals; no allocations allowed) ----
__device__ __half g_Ah[(size_t)N_ROWS * D_DIM];   // 16 MB
__device__ __half g_Bh[(size_t)K_CODES * D_DIM];  // 4 MB
__device__ unsigned long long g_tb[(size_t)N_ROWS * COL_TILES];  // 16 MB
__device__ unsigned long long g_best[N_ROWS];
__device__ int  g_list[(size_t)COL_TILES * N_ROWS];              // 8 MB
__device__ unsigned int g_cnt[COL_TILES];
__device__ float g_hn[K_CODES];
__device__ float g_nt[K_CODES];
__device__ float g_st[K_CODES * D_DIM];
__device__ float g_sse;
__device__ float g_nsum;

// ============================ PTX helpers (base ISA only) ============================
__device__ __forceinline__ uint32_t smem_u32(const void* p) {
    uint32_t a;
    asm("{ .reg .u64 t; cvta.to.shared.u64 t, %1; cvt.u32.u64 %0, t; }"
        : "=r"(a) : "l"(p));
    return a;
}

#define CP_ASYNC16(s, g) \
    asm volatile("cp.async.cg.shared.global [%0], [%1], 16;" :: "r"(s), "l"(g))
#define CP_COMMIT() asm volatile("cp.async.commit_group;" ::: "memory")
#define CP_WAIT(n)  asm volatile("cp.async.wait_group %0;" :: "n"(n) : "memory")

#define LDSM_X4(r0, r1, r2, r3, addr) \
    asm volatile("ldmatrix.sync.aligned.m8n8.x4.shared.b16 {%0,%1,%2,%3}, [%4];" \
                 : "=r"(r0), "=r"(r1), "=r"(r2), "=r"(r3) : "r"(addr))

// fp16 in, fp16 accum: D,C = 2 regs (4 halves)
#define MMA_F16(c, a, b0, b1) \
    asm volatile("mma.sync.aligned.m16n8k16.row.col.f16.f16.f16.f16 " \
                 "{%0,%1}, {%2,%3,%4,%5}, {%6,%7}, {%0,%1};" \
                 : "+r"((c)[0]), "+r"((c)[1]) \
                 : "r"((a)[0]), "r"((a)[1]), "r"((a)[2]), "r"((a)[3]), \
                   "r"(b0), "r"(b1))

__device__ __forceinline__ unsigned long long pack_key(float s, int col) {
    unsigned u = __float_as_uint(s);
    unsigned key = (u & 0x80000000u) ? ~u : (u | 0x80000000u);
    return ((unsigned long long)key << 32) | (unsigned)(0x0FFFFFFF - col);
}
__device__ __forceinline__ float key_score(unsigned long long pk) {
    unsigned key = (unsigned)(pk >> 32);
    unsigned u = (key & 0x80000000u) ? (key & 0x7FFFFFFFu) : ~key;
    return __uint_as_float(u);
}

__device__ __forceinline__ uint32_t sw128(uint32_t off) {
    return off ^ ((off >> 3) & 0x70);
}

// ---------------------------------------------------------------------------
// 1) half squared norms: hn[k] = 0.5 * ||W_k||^2   (exact fp32)
// ---------------------------------------------------------------------------
__global__ void compute_hn(const float* __restrict__ W) {
    int row  = blockIdx.x * 8 + (threadIdx.x >> 5);
    int lane = threadIdx.x & 31;
    const float4* wr = (const float4*)W + (size_t)row * 64;
    float4 a = wr[lane];
    float4 b = wr[lane + 32];
    float s = a.x*a.x + a.y*a.y + a.z*a.z + a.w*a.w
            + b.x*b.x + b.y*b.y + b.z*b.z + b.w*b.w;
    #pragma unroll
    for (int off = 16; off > 0; off >>= 1)
        s += __shfl_down_sync(0xffffffffu, s, off);
    if (lane == 0) g_hn[row] = 0.5f * s;
}

// ---------------------------------------------------------------------------
// 2) fp16 rounding (phase-1 GEMM input)
// ---------------------------------------------------------------------------
__global__ void split_A(const float4* __restrict__ z4) {
    int i = blockIdx.x * 256 + threadIdx.x;   // N_ROWS*64 float4s
    float4 v = z4[i];
    __half2 lo = __floats2half2_rn(v.x, v.y);
    __half2 hi = __floats2half2_rn(v.z, v.w);
    uint2 pk = { *(uint32_t*)&lo, *(uint32_t*)&hi };
    ((uint2*)g_Ah)[i] = pk;
}
__global__ void split_B(const float4* __restrict__ w4) {
    int i = blockIdx.x * 256 + threadIdx.x;   // K_CODES*64 float4s
    float4 v = w4[i];
    __half2 lo = __floats2half2_rn(v.x, v.y);
    __half2 hi = __floats2half2_rn(v.z, v.w);
    uint2 pk = { *(uint32_t*)&lo, *(uint32_t*)&hi };
    ((uint2*)g_Bh)[i] = pk;
}

// ---------------------------------------------------------------------------
// 3) Phase-1: fp16 GEMM (K=256, fp16 accum) + per-(row, col-tile) approx best.
//    CTA 128x128, BK=64 fp16 (128B rows, SW128), 8 warps (2m x 4n),
//    3-stage cp.async pipeline, mma.m16n8k16.f16 (fp16 accumulators).
//    All 24 LDSM swizzled offsets precomputed in registers.
// ---------------------------------------------------------------------------
#define STAGE_SZ 32768              // A 16KB + B 16KB
#define SM_HN    (3 * STAGE_SZ)
#define SM_TOTAL (SM_HN + 512)

__device__ __forceinline__ void load_chunk(uint32_t sstage,
                                           const __half* __restrict__ Agp,
                                           const __half* __restrict__ Bgp,
                                           int tid) {
    #pragma unroll
    for (int gi = 0; gi < 4; gi++) {
        int q = tid + gi * 256;          // 0..1023 granules per matrix
        int r = q >> 3, c = q & 7;       // row, 16B-chunk (8 fp16)
        uint32_t sw = sw128((uint32_t)(r * 128 + c * 16));
        CP_ASYNC16(sstage + sw,         Agp + (size_t)r * D_DIM + c * 8);
        CP_ASYNC16(sstage + 16384 + sw, Bgp + (size_t)r * D_DIM + c * 8);
    }
}

__global__ __launch_bounds__(256, 2) void gemm_p1() {
    extern __shared__ char smem[];
    const uint32_t sb = smem_u32(smem);
    const int tid = threadIdx.x, lid = tid & 31, wid = tid >> 5;
    const int wm = wid & 1, wn = wid >> 1;
    const int colT = blockIdx.x & (COL_TILES - 1);
    const int rowT = blockIdx.x >> 6;
    const int row0 = rowT * 128, col0 = colT * 128;

    if (blockIdx.x == 0 && tid < COL_TILES) g_cnt[tid] = 0;  // for rowreduce

    float* hn_s = (float*)(smem + SM_HN);
    if (tid < 128) hn_s[tid] = g_hn[col0 + tid];

    const __half* Ag = g_Ah + (size_t)row0 * D_DIM;
    const __half* Bg = g_Bh + (size_t)col0 * D_DIM;

    load_chunk(sb,            Ag,      Bg,      tid); CP_COMMIT();
    load_chunk(sb + STAGE_SZ, Ag + 64, Bg + 64, tid); CP_COMMIT();

    uint32_t c[4][4][2];
    #pragma unroll
    for (int i = 0; i < 4; i++)
        #pragma unroll
        for (int j = 0; j < 4; j++) { c[i][j][0] = 0u; c[i][j][1] = 0u; }

    // precomputed swizzled LDSM offsets (stage-relative); 1 IADD per use
    const int rA  = (lid & 7) + ((lid >> 3) & 1) * 8;   // + wm*64 + mt*16
    const int cA  = (lid >> 4) & 1;
    const int rB  = (lid & 7) + ((lid >> 4) & 1) * 8;   // + wn*32 + p*16
    const int cB  = (lid >> 3) & 1;
    uint32_t offA[4][4], offB[4][2];
    #pragma unroll
    for (int ks = 0; ks < 4; ks++) {
        #pragma unroll
        for (int mt = 0; mt < 4; mt++)
            offA[ks][mt] = sw128((uint32_t)((wm * 64 + mt * 16 + rA) * 128
                                            + ks * 32 + cA * 16));
        #pragma unroll
        for (int p = 0; p < 2; p++)
            offB[ks][p] = 16384u + sw128((uint32_t)((wn * 32 + p * 16 + rB) * 128
                                                    + ks * 32 + cB * 16));
    }

    for (int ch = 0; ch < NCH; ch++) {
        if (ch < NCH - 1) CP_WAIT(1); else CP_WAIT(0);
        __syncthreads();
        if (ch + 2 < NCH) {
            load_chunk(sb + ((ch + 2) % 3) * STAGE_SZ,
                       Ag + (ch + 2) * 64, Bg + (ch + 2) * 64, tid);
            CP_COMMIT();
        }
        const uint32_t sS = sb + (ch % 3) * STAGE_SZ;

        #pragma unroll
        for (int ks = 0; ks < 4; ks++) {              // 4 x k16 = 64
            uint32_t a[4][4], b[2][4];
            #pragma unroll
            for (int mt = 0; mt < 4; mt++)
                LDSM_X4(a[mt][0], a[mt][1], a[mt][2], a[mt][3], sS + offA[ks][mt]);
            #pragma unroll
            for (int p = 0; p < 2; p++)
                LDSM_X4(b[p][0], b[p][1], b[p][2], b[p][3], sS + offB[ks][p]);
            #pragma unroll
            for (int mt = 0; mt < 4; mt++)
                #pragma unroll
                for (int nt = 0; nt < 4; nt++)
                    MMA_F16(c[mt][nt], a[mt],
                            b[nt >> 1][(nt & 1) * 2 + 0],
                            b[nt >> 1][(nt & 1) * 2 + 1]);
        }
    }

    // ---- epilogue: per-row approx best within this 128-col tile ----
    __syncthreads();
    unsigned long long* sbest = (unsigned long long*)smem;
    if (tid < 128) sbest[tid] = 0ull;
    __syncthreads();

    const int g = lid >> 2, t = lid & 3;
    #pragma unroll
    for (int mt = 0; mt < 4; mt++) {
        #pragma unroll
        for (int rr = 0; rr < 2; rr++) {
            float best = -3.0e38f;
            int bc = 0;
            #pragma unroll
            for (int nt = 0; nt < 4; nt++) {
                __half2 h2 = *(__half2*)&c[mt][nt][rr];
                float v0 = __low2float(h2);
                float v1 = __high2float(h2);
                #pragma unroll
                for (int j = 0; j < 2; j++) {
                    int ccol = wn * 32 + nt * 8 + 2 * t + j;
                    float v = (j ? v1 : v0) - hn_s[ccol];
                    if (v > best) { best = v; bc = ccol; }
                }
            }
            #pragma unroll
            for (int off = 1; off <= 2; off <<= 1) {
                float ov = __shfl_xor_sync(0xffffffffu, best, off);
                int   oc = __shfl_xor_sync(0xffffffffu, bc, off);
                if (ov > best || (ov == best && oc < bc)) { best = ov; bc = oc; }
            }
            if (t == 0)
                atomicMax(&sbest[wm * 64 + mt * 16 + rr * 8 + g],
                          pack_key(best, col0 + bc));
        }
    }
    __syncthreads();
    if (tid < 128)
        g_tb[(size_t)(row0 + tid) * COL_TILES + colT] = sbest[tid];
}

// ---------------------------------------------------------------------------
// 4) per-row reduce over 64 tiles; build candidate tile lists (margin filter)
// ---------------------------------------------------------------------------
__global__ void rowreduce() {
    int row  = blockIdx.x * 8 + (threadIdx.x >> 5);
    int lane = threadIdx.x & 31;
    if (blockIdx.x == 0 && threadIdx.x == 0) g_sse = 0.0f;

    unsigned long long a = g_tb[(size_t)row * COL_TILES + lane];
    unsigned long long b = g_tb[(size_t)row * COL_TILES + lane + 32];
    unsigned long long m = a > b ? a : b;
    #pragma unroll
    for (int off = 16; off > 0; off >>= 1) {
        unsigned long long o = __shfl_xor_sync(0xffffffffu, m, off);
        if (o > m) m = o;
    }
    float thr = key_score(m) - MARGIN;
    if (key_score(a) >= thr) {
        unsigned slot = atomicAdd(&g_cnt[lane], 1u);
        g_list[(size_t)lane * N_ROWS + slot] = row;
    }
    if (key_score(b) >= thr) {
        unsigned slot = atomicAdd(&g_cnt[lane + 32], 1u);
        g_list[(size_t)(lane + 32) * N_ROWS + slot] = row;
    }
    if (lane == 0) g_best[row] = 0ull;
}

// ---------------------------------------------------------------------------
// 5) exact fp32 rescore of candidate (row, tile) pairs; merge via atomicMax
//    grid = 64 tiles x 8 CTAs; block 256 (8 warps); 8-row batches per warp.
// ---------------------------------------------------------------------------
#define WT_STRIDE 257
#define RS_WT_FLOATS (128 * WT_STRIDE)                 // 32896
#define RS_Z_OFF   RS_WT_FLOATS
#define RS_HN_OFF  (RS_Z_OFF + 8 * 8 * 256)
#define RS_SMEM    ((RS_HN_OFF + 128) * 4)             // bytes

__global__ __launch_bounds__(256, 1) void rescore(const float* __restrict__ ze,
                                                  const float* __restrict__ W) {
    extern __shared__ float sm[];
    float* Wt   = sm;
    float* zall = sm + RS_Z_OFF;
    float* hn_s = sm + RS_HN_OFF;

    const int tid = threadIdx.x, lane = tid & 31, warp = tid >> 5;
    const int tile = blockIdx.x >> 3, sub = blockIdx.x & 7;
    const int col0 = tile * 128;
    const unsigned cnt = g_cnt[tile];

    // load W tile [128 cols][256 d] fp32 -> stride-257 smem (conflict-free)
    const float4* W4 = (const float4*)W;
    for (int idx = tid; idx < 128 * 64; idx += 256) {
        int col = idx >> 6, d4 = idx & 63;
        float4 v = W4[(size_t)(col0 + col) * 64 + d4];
        float* p = Wt + col * WT_STRIDE + d4 * 4;
        p[0] = v.x; p[1] = v.y; p[2] = v.z; p[3] = v.w;
    }
    if (tid < 128) hn_s[tid] = g_hn[col0 + tid];
    __syncthreads();

    const float4* z4 = (const float4*)ze;
    float* zb = zall + warp * (8 * 256);
    const int warpg = sub * 8 + warp;                 // 0..63
    const unsigned nbatch = (cnt + 7) >> 3;

    for (unsigned b = warpg; b < nbatch; b += 64) {
        int rows[8];
        int nval = (int)cnt - (int)(b * 8);
        if (nval > 8) nval = 8;
        #pragma unroll
        for (int r = 0; r < 8; r++) {
            int li = (int)(b * 8) + r;
            rows[r] = g_list[(size_t)tile * N_ROWS + (r < nval ? li : (int)(b * 8))];
        }
        #pragma unroll
        for (int r = 0; r < 8; r++) {
            float4 z0 = z4[(size_t)rows[r] * 64 + lane * 2];
            float4 z1 = z4[(size_t)rows[r] * 64 + lane * 2 + 1];
            *(float4*)(zb + r * 256 + lane * 8)     = z0;
            *(float4*)(zb + r * 256 + lane * 8 + 4) = z1;
        }
        __syncwarp();

        float acc[8][4];
        #pragma unroll
        for (int r = 0; r < 8; r++)
            #pragma unroll
            for (int q = 0; q < 4; q++) acc[r][q] = 0.0f;

        for (int d4 = 0; d4 < 64; d4++) {
            float w[4][4];
            #pragma unroll
            for (int q = 0; q < 4; q++) {
                const float* wp = Wt + (lane + 32 * q) * WT_STRIDE + d4 * 4;
                w[q][0] = wp[0]; w[q][1] = wp[1]; w[q][2] = wp[2]; w[q][3] = wp[3];
            }
            #pragma unroll
            for (int r = 0; r < 8; r++) {
                float4 z = *(const float4*)(zb + r * 256 + d4 * 4);
                #pragma unroll
                for (int q = 0; q < 4; q++)
                    acc[r][q] += z.x * w[q][0] + z.y * w[q][1]
                               + z.z * w[q][2] + z.w * w[q][3];
            }
        }

        #pragma unroll
        for (int r = 0; r < 8; r++) {
            if (r >= nval) break;        // warp-uniform
            float best = -3.0e38f;
            int bc = 0;
            #pragma unroll
            for (int q = 0; q < 4; q++) {
                int ccol = lane + 32 * q;
                float s = acc[r][q] - hn_s[ccol];
                if (s > best) { best = s; bc = ccol; }
            }
            #pragma unroll
            for (int off = 1; off <= 16; off <<= 1) {
                float ov = __shfl_xor_sync(0xffffffffu, best, off);
                int   oc = __shfl_xor_sync(0xffffffffu, bc, off);
                if (ov > best || (ov == best && oc < bc)) { best = ov; bc = oc; }
            }
            if (lane == 0)
                atomicMax(&g_best[rows[r]], pack_key(best, col0 + bc));
        }
        __syncwarp();
    }
}

// ---------------------------------------------------------------------------
// 6) gather zq, commit-loss partials, scatter EMA sums/counts
//    4 rows per 256-thread block (64-thread slices) for better load MLP.
// ---------------------------------------------------------------------------
__global__ void gather_scatter(const float* __restrict__ ze,
                               const float* __restrict__ W,
                               float* __restrict__ out)
{
    __shared__ float wsum[4][2];
    const int slice = threadIdx.x >> 6;   // 0..3
    const int t     = threadIdx.x & 63;   // float4 per thread
    const int row   = blockIdx.x * 4 + slice;
    if (row == 0 && t == 0) g_nsum = 0.0f;
    unsigned long long pk = g_best[row];
    int k = 0x0FFFFFFF - (int)(unsigned)(pk & 0xFFFFFFFFu);

    float4 z = ((const float4*)ze)[(size_t)row * 64 + t];
    float4 w = ((const float4*)W)[(size_t)k * 64 + t];

    ((float4*)(out + OFF_ZQ))[(size_t)row * 64 + t] = w;

    float dx = w.x - z.x, dy = w.y - z.y, dz = w.z - z.z, dw = w.w - z.w;
    float ss = dx*dx + dy*dy + dz*dz + dw*dw;

    int base = k * D_DIM + 4 * t;
    atomicAdd(&g_st[base + 0], z.x);
    atomicAdd(&g_st[base + 1], z.y);
    atomicAdd(&g_st[base + 2], z.z);
    atomicAdd(&g_st[base + 3], z.w);

    #pragma unroll
    for (int off = 16; off > 0; off >>= 1)
        ss += __shfl_down_sync(0xffffffffu, ss, off);
    if ((t & 31) == 0) wsum[slice][t >> 5] = ss;
    __syncthreads();
    if (t == 0) {
        atomicAdd(&g_sse, wsum[slice][0] + wsum[slice][1]);
        atomicAdd(&g_nt[k], 1.0f);
        out[OFF_IDX + row] = (float)k;
    }
}

// ---------------------------------------------------------------------------
// 7) Nt_new + total count n + commit scalar
// ---------------------------------------------------------------------------
__global__ void finalizeN(const float* __restrict__ Nt, float* __restrict__ out) {
    int k = blockIdx.x * 256 + threadIdx.x;
    float v = GAMMA_F * Nt[k] + (1.0f - GAMMA_F) * g_nt[k];
    out[OFF_NT + k] = v;

    float s = v;
    #pragma unroll
    for (int off = 16; off > 0; off >>= 1)
        s += __shfl_down_sync(0xffffffffu, s, off);
    __shared__ float bs[8];
    if ((threadIdx.x & 31) == 0) bs[threadIdx.x >> 5] = s;
    __syncthreads();
    if (threadIdx.x == 0) {
        float b = 0.0f;
        #pragma unroll
        for (int w = 0; w < 8; w++) b += bs[w];
        atomicAdd(&g_nsum, b);
    }
    if (blockIdx.x == 0 && threadIdx.x == 0)
        out[OFF_COMMIT] = g_sse * (1.0f / (float)(N_ROWS * D_DIM));
}

// ---------------------------------------------------------------------------
// 8) mt_new, embedW_new = mt_new / Nn; read-then-zero the EMA scratch
// ---------------------------------------------------------------------------
__global__ void finalizeW(const float* __restrict__ mt,
                          const float* __restrict__ Nt,
                          float* __restrict__ out)
{
    int k = blockIdx.x;
    int d = threadIdx.x;
    float n   = g_nsum;
    float Ntn = GAMMA_F * Nt[k] + (1.0f - GAMMA_F) * g_nt[k];
    float inv = (n + (float)K_CODES * EPS_F) / ((Ntn + EPS_F) * n);
    int q = k * D_DIM + d;
    float m = GAMMA_F * mt[q] + (1.0f - GAMMA_F) * g_st[q];
    out[OFF_MT  + q] = m;
    out[OFF_EMB + q] = m * inv;
    g_st[q] = 0.0f;                       // re-zero for next graph replay
    __syncthreads();
    if (d == 0) g_nt[k] = 0.0f;
}

// ---------------------------------------------------------------------------
extern "C" void kernel_launch(void* const* d_in, const int* in_sizes, int n_in,
                              void* d_out, int out_size)
{
    const float* ze = (const float*)d_in[0];
    const float* W  = (const float*)d_in[1];
    const float* mt = (const float*)d_in[2];
    const float* Nt = (const float*)d_in[3];
    float* out = (float*)d_out;

    cudaFuncSetAttribute(gemm_p1,
                         cudaFuncAttributeMaxDynamicSharedMemorySize, SM_TOTAL);
    cudaFuncSetAttribute(rescore,
                         cudaFuncAttributeMaxDynamicSharedMemorySize, RS_SMEM);

    compute_hn    <<<K_CODES / 8, 256>>> (W);
    split_A       <<<N_ROWS * 64 / 256, 256>>> ((const float4*)ze);
    split_B       <<<K_CODES * 64 / 256, 256>>> ((const float4*)W);
    gemm_p1       <<<ROW_TILES * COL_TILES, 256, SM_TOTAL>>> ();
    rowreduce     <<<N_ROWS / 8, 256>>> ();
    rescore       <<<COL_TILES * 8, 256, RS_SMEM>>> (ze, W);
    gather_scatter<<<N_ROWS / 4, 256>>> (ze, W, out);
    finalizeN     <<<K_CODES / 256, 256>>> (Nt, out);
    finalizeW     <<<K_CODES, 256>>> (mt, Nt, out);
}